// round 5
// baseline (speedup 1.0000x reference)
#include <cuda_runtime.h>
#include <cuda_fp16.h>
#include <cstdint>
#include <cstddef>

#define NUc 100000
#define NTc 200000
#define Ec  1000000

typedef unsigned long long u64;
typedef unsigned int u32;

// ---------------- scratch (device globals; no allocation) ----------------
__device__ __align__(128) float g_hu [NUc*64];
__device__ __align__(128) float g_ht [NTc*64];
// transformed messages, fp16 packed (half2 pairs), row = 32 u32
__device__ __align__(128) u32 g_mu0h[NUc*32];   // (hu@W_u2u) * d_u2u[row]
__device__ __align__(128) u32 g_mu1h[NUc*32];   // (hu@W_u2t) * ds_u2t[row]
__device__ __align__(128) u32 g_mt0h[NTc*32];   // (ht@W_t2t) * d_t2t[row]
__device__ __align__(128) u32 g_mt1h[NTc*32];   // (ht@W_t2u) * ds_t2u[row]

__device__ int g_c_u2u[NUc];
__device__ int g_c_t2t[NTc];
__device__ int g_c_u2t_d[NTc];
__device__ int g_c_t2u_d[NUc];
__device__ int g_c_u2t_s[NUc];
__device__ int g_c_t2u_s[NTc];

__device__ float g_d_u2u[NUc];    // rsqrt(deg+1) (incl self loop)
__device__ float g_d_t2t[NTc];
__device__ float g_ds_u2t[NUc];
__device__ float g_dd_u2t[NTc];
__device__ float g_ds_t2u[NTc];
__device__ float g_dd_t2u[NUc];

__device__ int g_off_u2u[NUc+1];
__device__ int g_off_t2t[NTc+1];
__device__ int g_off_u2t[NTc+1];
__device__ int g_off_t2u[NUc+1];
__device__ int g_cur_u2u[NUc];
__device__ int g_cur_t2t[NTc];
__device__ int g_cur_u2t[NTc];
__device__ int g_cur_t2u[NUc];
__device__ int g_csr_u2u[Ec];
__device__ int g_csr_t2t[Ec];
__device__ int g_csr_u2t[Ec];
__device__ int g_csr_t2u[Ec];

__device__ float g_colsum[128];

// ---------------- helpers ----------------
__device__ __forceinline__ u32 f2tf(float f) {
    u32 u; asm("cvt.rna.tf32.f32 %0,%1;" : "=r"(u) : "f"(f)); return u;
}
__device__ __forceinline__ void mma_tf32(float* c, u32 a0, u32 a1, u32 a2, u32 a3,
                                         u32 b0, u32 b1) {
    asm volatile(
        "mma.sync.aligned.m16n8k8.row.col.f32.tf32.tf32.f32 "
        "{%0,%1,%2,%3}, {%4,%5,%6,%7}, {%8,%9}, {%0,%1,%2,%3};"
        : "+f"(c[0]), "+f"(c[1]), "+f"(c[2]), "+f"(c[3])
        : "r"(a0), "r"(a1), "r"(a2), "r"(a3), "r"(b0), "r"(b1));
}
__device__ __forceinline__ void acc_h8(float* acc, uint4 v) {
    float2 f;
    f = __half22float2(*(__half2*)&v.x); acc[0] += f.x; acc[1] += f.y;
    f = __half22float2(*(__half2*)&v.y); acc[2] += f.x; acc[3] += f.y;
    f = __half22float2(*(__half2*)&v.z); acc[4] += f.x; acc[5] += f.y;
    f = __half22float2(*(__half2*)&v.w); acc[6] += f.x; acc[7] += f.y;
}

// ---------------- setup: counts ----------------
__global__ void zero_cnt_kernel() {
    int i = blockIdx.x * blockDim.x + threadIdx.x;
    if (i < NUc) { g_c_u2u[i] = 0; g_c_u2t_s[i] = 0; g_c_t2u_d[i] = 0; }
    if (i < NTc) { g_c_t2t[i] = 0; g_c_u2t_d[i] = 0; g_c_t2u_s[i] = 0; }
    if (i < 128) g_colsum[i] = 0.f;
}

__global__ void count_kernel(const int* __restrict__ eu2u, const int* __restrict__ et2t,
                             const int* __restrict__ eu2t, const int* __restrict__ et2u) {
    int e = blockIdx.x * blockDim.x + threadIdx.x;
    if (e >= Ec) return;
    atomicAdd(&g_c_u2u[eu2u[Ec + e]], 1);
    atomicAdd(&g_c_t2t[et2t[Ec + e]], 1);
    atomicAdd(&g_c_u2t_d[eu2t[Ec + e]], 1);
    atomicAdd(&g_c_u2t_s[eu2t[e]],      1);
    atomicAdd(&g_c_t2u_d[et2u[Ec + e]], 1);
    atomicAdd(&g_c_t2u_s[et2u[e]],      1);
}

// ---------------- setup: 4 exclusive scans (one block each) ----------------
__global__ void scan4_kernel() {
    const int* cnt; int* off; int* cur; int n;
    switch (blockIdx.x) {
        case 0:  cnt = g_c_u2u;   off = g_off_u2u; cur = g_cur_u2u; n = NUc; break;
        case 1:  cnt = g_c_t2t;   off = g_off_t2t; cur = g_cur_t2t; n = NTc; break;
        case 2:  cnt = g_c_u2t_d; off = g_off_u2t; cur = g_cur_u2t; n = NTc; break;
        default: cnt = g_c_t2u_d; off = g_off_t2u; cur = g_cur_t2u; n = NUc; break;
    }
    __shared__ int sh[1024];
    int tid = threadIdx.x;
    int chunk = (n + 1023) >> 10;
    int start = tid * chunk;
    int end = min(start + chunk, n);
    int s = 0;
    for (int i = start; i < end; i++) s += cnt[i];
    sh[tid] = s;
    __syncthreads();
    for (int d = 1; d < 1024; d <<= 1) {
        int v = (tid >= d) ? sh[tid - d] : 0;
        __syncthreads();
        sh[tid] += v;
        __syncthreads();
    }
    int run = sh[tid] - s;   // exclusive prefix of this chunk
    for (int i = start; i < end; i++) { off[i] = run; cur[i] = run; run += cnt[i]; }
    if (start < n && end == n) off[n] = run;
}

// ---------------- setup: CSR fill ----------------
__global__ void fill_kernel(const int* __restrict__ eu2u, const int* __restrict__ et2t,
                            const int* __restrict__ eu2t, const int* __restrict__ et2u) {
    int e = blockIdx.x * blockDim.x + threadIdx.x;
    if (e >= Ec) return;
    int p;
    p = atomicAdd(&g_cur_u2u[eu2u[Ec + e]], 1); g_csr_u2u[p] = eu2u[e];
    p = atomicAdd(&g_cur_t2t[et2t[Ec + e]], 1); g_csr_t2t[p] = et2t[e];
    p = atomicAdd(&g_cur_u2t[eu2t[Ec + e]], 1); g_csr_u2t[p] = eu2t[e];
    p = atomicAdd(&g_cur_t2u[et2u[Ec + e]], 1); g_csr_t2u[p] = et2u[e];
}

__global__ void dinv_kernel() {
    int i = blockIdx.x * blockDim.x + threadIdx.x;
    if (i < NUc) {
        g_d_u2u[i] = rsqrtf((float)g_c_u2u[i] + 1.f);
        int cs = g_c_u2t_s[i]; g_ds_u2t[i] = (cs > 0) ? rsqrtf((float)cs) : 0.f;
        int cd = g_c_t2u_d[i]; g_dd_t2u[i] = (cd > 0) ? rsqrtf((float)cd) : 0.f;
    }
    if (i < NTc) {
        g_d_t2t[i] = rsqrtf((float)g_c_t2t[i] + 1.f);
        int cd = g_c_u2t_d[i]; g_dd_u2t[i] = (cd > 0) ? rsqrtf((float)cd) : 0.f;
        int cs = g_c_t2u_s[i]; g_ds_t2u[i] = (cs > 0) ? rsqrtf((float)cs) : 0.f;
    }
}

// ---------------- tf32 tensor-core GEMM core: 128-row tile, K=64, N=64 ----------------
template<bool DUAL>
__device__ __forceinline__ void mma_gemm64(const float* __restrict__ A,
                                           const float* __restrict__ W0,
                                           const float* __restrict__ W1,
                                           const float* __restrict__ sc0,
                                           const float* __restrict__ sc1,
                                           const float* __restrict__ bias,
                                           u32* __restrict__ O0h,
                                           u32* __restrict__ O1h,
                                           float* __restrict__ O0f,
                                           int N, int tile) {
    extern __shared__ float sm[];
    float* Wf0 = sm;
    float* Wf1 = DUAL ? (sm + 4096) : sm;
    float* As  = sm + (DUAL ? 8192 : 4096);   // 128*72 floats; reused as staging
    int t = threadIdx.x;
    int lane = t & 31, wid = t >> 5;
    int row0 = tile * 128;

    // pack weight fragments
    for (int i = t; i < 2048; i += 256) {
        int kk = i >> 8, rem = i & 255;
        int nt = rem >> 5, ln = rem & 31;
        int k0 = ln & 3, n = ln >> 2;
        int col = nt * 8 + n, k = kk * 8 + k0;
        float2 v;
        v.x = __uint_as_float(f2tf(W0[k * 64 + col]));
        v.y = __uint_as_float(f2tf(W0[(k + 4) * 64 + col]));
        *(float2*)&Wf0[(size_t)i * 2] = v;
        if (DUAL) {
            v.x = __uint_as_float(f2tf(W1[k * 64 + col]));
            v.y = __uint_as_float(f2tf(W1[(k + 4) * 64 + col]));
            *(float2*)&Wf1[(size_t)i * 2] = v;
        }
    }
    // load + convert A tile
    for (int i = t; i < 128 * 64; i += 256) {
        int r = i >> 6, c = i & 63;
        int gr = row0 + r;
        float v = (gr < N) ? A[((size_t)gr << 6) + c] : 0.f;
        As[r * 72 + c] = __uint_as_float(f2tf(v));
    }
    __syncthreads();

    const u32* Asu = (const u32*)As;
    int rbase = wid * 16;
    int fr = lane >> 2, fc = lane & 3;

    float acc0[8][4];
    float acc1[DUAL ? 8 : 1][4];
#pragma unroll
    for (int nt = 0; nt < 8; nt++)
#pragma unroll
        for (int j = 0; j < 4; j++) { acc0[nt][j] = 0.f; if (DUAL) acc1[nt][j] = 0.f; }

#pragma unroll
    for (int kk = 0; kk < 8; kk++) {
        int base = (rbase + fr) * 72 + kk * 8 + fc;
        u32 a0 = Asu[base];
        u32 a1 = Asu[base + 8 * 72];
        u32 a2 = Asu[base + 4];
        u32 a3 = Asu[base + 8 * 72 + 4];
#pragma unroll
        for (int nt = 0; nt < 8; nt++) {
            float2 b = *(const float2*)&Wf0[(size_t)(((kk << 3) + nt) << 5 | lane) * 2];
            mma_tf32(acc0[nt], a0, a1, a2, a3, __float_as_uint(b.x), __float_as_uint(b.y));
            if (DUAL) {
                float2 c = *(const float2*)&Wf1[(size_t)(((kk << 3) + nt) << 5 | lane) * 2];
                mma_tf32(acc1[nt], a0, a1, a2, a3, __float_as_uint(c.x), __float_as_uint(c.y));
            }
        }
    }

    // ---- epilogue: stage D through smem, coalesced stores ----
    float* st = As;
    __syncthreads();
#pragma unroll
    for (int nt = 0; nt < 8; nt++) {
        int cbase = nt * 8 + fc * 2;
        *(float2*)&st[(rbase + fr) * 72 + cbase]     = make_float2(acc0[nt][0], acc0[nt][1]);
        *(float2*)&st[(rbase + fr + 8) * 72 + cbase] = make_float2(acc0[nt][2], acc0[nt][3]);
    }
    __syncthreads();
    for (int i = t; i < 128 * 16; i += 256) {
        int r = i >> 4, c4 = (i & 15) << 2;
        int gr = row0 + r;
        if (gr < N) {
            float4 v = *(float4*)&st[r * 72 + c4];
            if (!DUAL) {
                float4 bv = *(const float4*)(bias + c4);
                v.x += bv.x; v.y += bv.y; v.z += bv.z; v.w += bv.w;
                *(float4*)&O0f[((size_t)gr << 6) + c4] = v;
            } else {
                float s = sc0[gr];
                __half2 h0 = __floats2half2_rn(v.x * s, v.y * s);
                __half2 h1 = __floats2half2_rn(v.z * s, v.w * s);
                uint2 pk;
                pk.x = *(u32*)&h0; pk.y = *(u32*)&h1;
                *(uint2*)&O0h[((size_t)gr << 5) + (c4 >> 1)] = pk;
            }
        }
    }
    if (DUAL) {
        __syncthreads();
#pragma unroll
        for (int nt = 0; nt < 8; nt++) {
            int cbase = nt * 8 + fc * 2;
            *(float2*)&st[(rbase + fr) * 72 + cbase]     = make_float2(acc1[nt][0], acc1[nt][1]);
            *(float2*)&st[(rbase + fr + 8) * 72 + cbase] = make_float2(acc1[nt][2], acc1[nt][3]);
        }
        __syncthreads();
        for (int i = t; i < 128 * 16; i += 256) {
            int r = i >> 4, c4 = (i & 15) << 2;
            int gr = row0 + r;
            if (gr < N) {
                float4 v = *(float4*)&st[r * 72 + c4];
                float s = sc1[gr];
                __half2 h0 = __floats2half2_rn(v.x * s, v.y * s);
                __half2 h1 = __floats2half2_rn(v.z * s, v.w * s);
                uint2 pk;
                pk.x = *(u32*)&h0; pk.y = *(u32*)&h1;
                *(uint2*)&O1h[((size_t)gr << 5) + (c4 >> 1)] = pk;
            }
        }
    }
}

#define GU_T ((NUc + 127) / 128)
#define GT_T ((NTc + 127) / 128)

// merged transforms for one layer: u tiles then t tiles
__global__ void __launch_bounds__(256) transform_kernel(const float* __restrict__ W) {
    int b = blockIdx.x;
    if (b < GU_T) {
        mma_gemm64<true>(g_hu, W + 0 * 4096, W + 2 * 4096, g_d_u2u, g_ds_u2t, nullptr,
                         g_mu0h, g_mu1h, nullptr, NUc, b);
    } else {
        mma_gemm64<true>(g_ht, W + 1 * 4096, W + 3 * 4096, g_d_t2t, g_ds_t2u, nullptr,
                         g_mt0h, g_mt1h, nullptr, NTc, b - GU_T);
    }
}

__global__ void __launch_bounds__(256) embed_txn_kernel(const float* __restrict__ x,
                                                        const float* __restrict__ W,
                                                        const float* __restrict__ b) {
    mma_gemm64<false>(x, W, nullptr, nullptr, nullptr, b, nullptr, nullptr, g_ht,
                      NTc, blockIdx.x);
}

// ---------------- fp32 embed for K=32 (small, one-time) ----------------
__global__ void __launch_bounds__(256) embed_user_kernel(const float* __restrict__ A,
                                                         const float* __restrict__ W,
                                                         const float* __restrict__ b) {
    const int K = 32;
    __shared__ float Ws[K * 64];
    __shared__ float As[32 * (K + 1)];
    int t = threadIdx.x;
    for (int i = t; i < K * 64; i += 256) Ws[i] = W[i];
    int row0 = blockIdx.x * 32;
    for (int i = t; i < 32 * K; i += 256) {
        int r = i / K, c = i - r * K; int gr = row0 + r;
        As[r * (K + 1) + c] = (gr < NUc) ? A[(size_t)gr * K + c] : 0.f;
    }
    __syncthreads();
    int r = t >> 3, cseg = (t & 7) << 3;
    float acc[8];
#pragma unroll
    for (int i = 0; i < 8; i++) acc[i] = b[cseg + i];
#pragma unroll
    for (int k = 0; k < K; k++) {
        float a = As[r * (K + 1) + k];
#pragma unroll
        for (int i = 0; i < 8; i++) acc[i] += a * Ws[(k << 6) + cseg + i];
    }
    int gr = row0 + r;
    if (gr < NUc) {
        float4* p = (float4*)(g_hu + ((size_t)gr << 6) + cseg);
        p[0] = make_float4(acc[0], acc[1], acc[2], acc[3]);
        p[1] = make_float4(acc[4], acc[5], acc[6], acc[7]);
    }
}

// ---------------- fused gather-aggregate + bias + relu (fp16 messages) ----------------
// 4 threads/node, 16 columns each; CSR indices prefetched 4-wide for MLP.
__device__ __forceinline__ void gather_loop(float* acc, const u32* __restrict__ m,
                                            const int* __restrict__ csr,
                                            int e, int end, int woff) {
    for (; e + 4 <= end; e += 4) {
        int s0 = __ldg(csr + e), s1 = __ldg(csr + e + 1);
        int s2 = __ldg(csr + e + 2), s3 = __ldg(csr + e + 3);
        const u32* p0 = m + ((size_t)s0 << 5) + woff;
        const u32* p1 = m + ((size_t)s1 << 5) + woff;
        const u32* p2 = m + ((size_t)s2 << 5) + woff;
        const u32* p3 = m + ((size_t)s3 << 5) + woff;
        uint4 x0 = __ldg((const uint4*)p0), x1 = __ldg((const uint4*)(p0 + 4));
        uint4 y0 = __ldg((const uint4*)p1), y1 = __ldg((const uint4*)(p1 + 4));
        uint4 z0 = __ldg((const uint4*)p2), z1 = __ldg((const uint4*)(p2 + 4));
        uint4 w0 = __ldg((const uint4*)p3), w1 = __ldg((const uint4*)(p3 + 4));
        acc_h8(acc, x0); acc_h8(acc + 8, x1);
        acc_h8(acc, y0); acc_h8(acc + 8, y1);
        acc_h8(acc, z0); acc_h8(acc + 8, z1);
        acc_h8(acc, w0); acc_h8(acc + 8, w1);
    }
    for (; e < end; e++) {
        int s = __ldg(csr + e);
        const u32* p = m + ((size_t)s << 5) + woff;
        uint4 x0 = __ldg((const uint4*)p), x1 = __ldg((const uint4*)(p + 4));
        acc_h8(acc, x0); acc_h8(acc + 8, x1);
    }
}

__device__ __forceinline__ void agg_body(int idx,
                                         const u32* __restrict__ mA,
                                         const int* __restrict__ offA,
                                         const int* __restrict__ csrA,
                                         const float* __restrict__ dA,
                                         const u32* __restrict__ mB,
                                         const int* __restrict__ offB,
                                         const int* __restrict__ csrB,
                                         const float* __restrict__ dB,
                                         const float* __restrict__ bA,
                                         const float* __restrict__ bB,
                                         float* __restrict__ Out, int N) {
    int g = idx >> 2;
    if (g >= N) return;
    int q = idx & 3;              // 16 columns per thread: two uint4 = 16 halves
    int woff = q << 3;            // u32 offset within row (row = 32 u32)
    float a[16], b[16];
    // self term (relation A includes self loop)
    {
        const u32* p = mA + ((size_t)g << 5) + woff;
        uint4 v0 = __ldg((const uint4*)p), v1 = __ldg((const uint4*)(p + 4));
        float2 f;
        f = __half22float2(*(__half2*)&v0.x); a[0] = f.x; a[1] = f.y;
        f = __half22float2(*(__half2*)&v0.y); a[2] = f.x; a[3] = f.y;
        f = __half22float2(*(__half2*)&v0.z); a[4] = f.x; a[5] = f.y;
        f = __half22float2(*(__half2*)&v0.w); a[6] = f.x; a[7] = f.y;
        f = __half22float2(*(__half2*)&v1.x); a[8] = f.x; a[9] = f.y;
        f = __half22float2(*(__half2*)&v1.y); a[10] = f.x; a[11] = f.y;
        f = __half22float2(*(__half2*)&v1.z); a[12] = f.x; a[13] = f.y;
        f = __half22float2(*(__half2*)&v1.w); a[14] = f.x; a[15] = f.y;
    }
#pragma unroll
    for (int i = 0; i < 16; i++) b[i] = 0.f;
    gather_loop(a, mA, csrA, offA[g], offA[g + 1], woff);
    gather_loop(b, mB, csrB, offB[g], offB[g + 1], woff);
    float da = dA[g], db = dB[g];
    int c0 = q << 4;
    float* op = Out + ((size_t)g << 6) + c0;
#pragma unroll
    for (int v = 0; v < 4; v++) {
        float4 bAv = __ldg((const float4*)(bA + c0 + v * 4));
        float4 bBv = __ldg((const float4*)(bB + c0 + v * 4));
        float4 o;
        o.x = fmaxf(0.5f * (da * a[v * 4 + 0] + db * b[v * 4 + 0] + bAv.x + bBv.x), 0.f);
        o.y = fmaxf(0.5f * (da * a[v * 4 + 1] + db * b[v * 4 + 1] + bAv.y + bBv.y), 0.f);
        o.z = fmaxf(0.5f * (da * a[v * 4 + 2] + db * b[v * 4 + 2] + bAv.z + bBv.z), 0.f);
        o.w = fmaxf(0.5f * (da * a[v * 4 + 3] + db * b[v * 4 + 3] + bAv.w + bBv.w), 0.f);
        *(float4*)(op + v * 4) = o;
    }
}

#define AU_B ((NUc * 4 + 255) / 256)
#define AT_B ((NTc * 4 + 255) / 256)

__global__ void __launch_bounds__(256) agg_kernel(const float* __restrict__ B) {
    int b = blockIdx.x;
    if (b < AU_B) {
        agg_body(b * 256 + threadIdx.x,
                 g_mu0h, g_off_u2u, g_csr_u2u, g_d_u2u,
                 g_mt1h, g_off_t2u, g_csr_t2u, g_dd_t2u,
                 B + 0 * 64, B + 3 * 64, g_hu, NUc);
    } else {
        agg_body((b - AU_B) * 256 + threadIdx.x,
                 g_mt0h, g_off_t2t, g_csr_t2t, g_d_t2t,
                 g_mu1h, g_off_u2t, g_csr_u2t, g_dd_u2t,
                 B + 1 * 64, B + 2 * 64, g_ht, NTc);
    }
}

// ---------------- readout ----------------
#define CS_BLOCKS 296
__global__ void colsum_kernel() {
    int b = blockIdx.x;
    if (b < CS_BLOCKS) {
        int t = b * blockDim.x + threadIdx.x;
        float s = 0.f;
        const int n = NUc * 64;
        for (int i = t; i < n; i += CS_BLOCKS * 256) s += g_hu[i];
        atomicAdd(&g_colsum[t & 63], s);
    } else {
        int t = (b - CS_BLOCKS) * blockDim.x + threadIdx.x;
        float s = 0.f;
        const int n = NTc * 64;
        for (int i = t; i < n; i += CS_BLOCKS * 256) s += g_ht[i];
        atomicAdd(&g_colsum[64 + (t & 63)], s);
    }
}

__global__ void mlp_kernel(const float* __restrict__ W1, const float* __restrict__ b1,
                           const float* __restrict__ W2, const float* __restrict__ b2,
                           float* __restrict__ out) {
    __shared__ float x[64];
    __shared__ float y[64];
    int t = threadIdx.x;
    x[t] = 0.5f * (g_colsum[t] * (1.f / NUc) + g_colsum[64 + t] * (1.f / NTc));
    __syncthreads();
    float s = b1[t];
    for (int k = 0; k < 64; k++) s += x[k] * W1[k * 64 + t];
    y[t] = fmaxf(s, 0.f) * W2[t];
    __syncthreads();
    if (t == 0) {
        float o = b2[0];
        for (int j = 0; j < 64; j++) o += y[j];
        out[0] = 1.f / (1.f + expf(-o));
    }
}

// ---------------- launch ----------------
extern "C" void kernel_launch(void* const* d_in, const int* in_sizes, int n_in,
                              void* d_out, int out_size) {
    const float* x_user     = (const float*)d_in[0];
    const float* x_txn      = (const float*)d_in[1];
    const int*   ei_u2u     = (const int*)d_in[2];
    const int*   ei_t2t     = (const int*)d_in[3];
    const int*   ei_u2t     = (const int*)d_in[4];
    const int*   ei_t2u     = (const int*)d_in[5];
    const float* W_emb_user = (const float*)d_in[6];
    const float* b_emb_user = (const float*)d_in[7];
    const float* W_emb_txn  = (const float*)d_in[8];
    const float* b_emb_txn  = (const float*)d_in[9];
    const float* conv_W     = (const float*)d_in[10];
    const float* conv_b     = (const float*)d_in[11];
    const float* W1         = (const float*)d_in[12];
    const float* b1         = (const float*)d_in[13];
    const float* W2         = (const float*)d_in[14];
    const float* b2         = (const float*)d_in[15];
    float* out = (float*)d_out;

    const int SMEM_DUAL = (2 * 4096 + 128 * 72) * 4;   // 69632
    const int SMEM_SNGL = (4096 + 128 * 72) * 4;       // 53248
    cudaFuncSetAttribute(transform_kernel, cudaFuncAttributeMaxDynamicSharedMemorySize, SMEM_DUAL);
    cudaFuncSetAttribute(embed_txn_kernel, cudaFuncAttributeMaxDynamicSharedMemorySize, SMEM_SNGL);

    // ---- CSR + norms (edge structure is layer-invariant) ----
    zero_cnt_kernel<<<(NTc + 255) / 256, 256>>>();
    count_kernel<<<(Ec + 255) / 256, 256>>>(ei_u2u, ei_t2t, ei_u2t, ei_t2u);
    scan4_kernel<<<4, 1024>>>();
    fill_kernel<<<(Ec + 255) / 256, 256>>>(ei_u2u, ei_t2t, ei_u2t, ei_t2u);
    dinv_kernel<<<(NTc + 255) / 256, 256>>>();

    // ---- embeddings ----
    embed_user_kernel<<<(NUc + 31) / 32, 256>>>(x_user, W_emb_user, b_emb_user);
    embed_txn_kernel<<<GT_T, 256, SMEM_SNGL>>>(x_txn, W_emb_txn, b_emb_txn);

    // ---- layers ----
    for (int l = 0; l < 3; l++) {
        const float* W = conv_W + (size_t)l * 4 * 64 * 64;
        const float* B = conv_b + (size_t)l * 4 * 64;
        transform_kernel<<<GU_T + GT_T, 256, SMEM_DUAL>>>(W);
        agg_kernel<<<AU_B + AT_B, 256>>>(B);
    }

    // ---- readout ----
    colsum_kernel<<<2 * CS_BLOCKS, 256>>>();
    mlp_kernel<<<1, 64>>>(W1, b1, W2, b2, out);
}

// round 6
// speedup vs baseline: 1.0479x; 1.0479x over previous
#include <cuda_runtime.h>
#include <cuda_fp16.h>
#include <cstdint>
#include <cstddef>

#define NUc 100000
#define NTc 200000
#define Ec  1000000

typedef unsigned long long u64;
typedef unsigned int u32;

// ---------------- scratch (device globals; no allocation) ----------------
__device__ __align__(128) float g_hu [NUc*64];
__device__ __align__(128) float g_ht [NTc*64];
// transformed messages, fp16 packed (half2 pairs), row = 32 u32
__device__ __align__(128) u32 g_mu0h[NUc*32];   // (hu@W_u2u) * d_u2u[row]
__device__ __align__(128) u32 g_mu1h[NUc*32];   // (hu@W_u2t) * ds_u2t[row]
__device__ __align__(128) u32 g_mt0h[NTc*32];   // (ht@W_t2t) * d_t2t[row]
__device__ __align__(128) u32 g_mt1h[NTc*32];   // (ht@W_t2u) * ds_t2u[row]

__device__ int g_c_u2u[NUc];
__device__ int g_c_t2t[NTc];
__device__ int g_c_u2t_d[NTc];
__device__ int g_c_t2u_d[NUc];
__device__ int g_c_u2t_s[NUc];
__device__ int g_c_t2u_s[NTc];

__device__ float g_d_u2u[NUc];    // rsqrt(deg+1) (incl self loop)
__device__ float g_d_t2t[NTc];
__device__ float g_ds_u2t[NUc];
__device__ float g_dd_u2t[NTc];
__device__ float g_ds_t2u[NTc];
__device__ float g_dd_t2u[NUc];

__device__ int g_off_u2u[NUc+1];
__device__ int g_off_t2t[NTc+1];
__device__ int g_off_u2t[NTc+1];
__device__ int g_off_t2u[NUc+1];
__device__ int g_cur_u2u[NUc];
__device__ int g_cur_t2t[NTc];
__device__ int g_cur_u2t[NTc];
__device__ int g_cur_t2u[NUc];
__device__ int g_csr_u2u[Ec];
__device__ int g_csr_t2t[Ec];
__device__ int g_csr_u2t[Ec];
__device__ int g_csr_t2u[Ec];

__device__ float g_colsum[128];

// ---------------- helpers ----------------
__device__ __forceinline__ u32 f2tf(float f) {
    u32 u; asm("cvt.rna.tf32.f32 %0,%1;" : "=r"(u) : "f"(f)); return u;
}
__device__ __forceinline__ void mma_tf32(float* c, u32 a0, u32 a1, u32 a2, u32 a3,
                                         u32 b0, u32 b1) {
    asm volatile(
        "mma.sync.aligned.m16n8k8.row.col.f32.tf32.tf32.f32 "
        "{%0,%1,%2,%3}, {%4,%5,%6,%7}, {%8,%9}, {%0,%1,%2,%3};"
        : "+f"(c[0]), "+f"(c[1]), "+f"(c[2]), "+f"(c[3])
        : "r"(a0), "r"(a1), "r"(a2), "r"(a3), "r"(b0), "r"(b1));
}
__device__ __forceinline__ void acc_h8(float* acc, uint4 v) {
    float2 f;
    f = __half22float2(*(__half2*)&v.x); acc[0] += f.x; acc[1] += f.y;
    f = __half22float2(*(__half2*)&v.y); acc[2] += f.x; acc[3] += f.y;
    f = __half22float2(*(__half2*)&v.z); acc[4] += f.x; acc[5] += f.y;
    f = __half22float2(*(__half2*)&v.w); acc[6] += f.x; acc[7] += f.y;
}
__device__ __forceinline__ uint4 h2add4(uint4 a, uint4 b) {
    uint4 r;
    *(__half2*)&r.x = __hadd2(*(__half2*)&a.x, *(__half2*)&b.x);
    *(__half2*)&r.y = __hadd2(*(__half2*)&a.y, *(__half2*)&b.y);
    *(__half2*)&r.z = __hadd2(*(__half2*)&a.z, *(__half2*)&b.z);
    *(__half2*)&r.w = __hadd2(*(__half2*)&a.w, *(__half2*)&b.w);
    return r;
}

// ---------------- setup: counts ----------------
__global__ void zero_cnt_kernel() {
    int i = blockIdx.x * blockDim.x + threadIdx.x;
    if (i < NUc) { g_c_u2u[i] = 0; g_c_u2t_s[i] = 0; g_c_t2u_d[i] = 0; }
    if (i < NTc) { g_c_t2t[i] = 0; g_c_u2t_d[i] = 0; g_c_t2u_s[i] = 0; }
    if (i < 128) g_colsum[i] = 0.f;
}

__global__ void count_kernel(const int* __restrict__ eu2u, const int* __restrict__ et2t,
                             const int* __restrict__ eu2t, const int* __restrict__ et2u) {
    int e = blockIdx.x * blockDim.x + threadIdx.x;
    if (e >= Ec) return;
    atomicAdd(&g_c_u2u[eu2u[Ec + e]], 1);
    atomicAdd(&g_c_t2t[et2t[Ec + e]], 1);
    atomicAdd(&g_c_u2t_d[eu2t[Ec + e]], 1);
    atomicAdd(&g_c_u2t_s[eu2t[e]],      1);
    atomicAdd(&g_c_t2u_d[et2u[Ec + e]], 1);
    atomicAdd(&g_c_t2u_s[et2u[e]],      1);
}

// ---------------- setup: 4 exclusive scans (one block each) ----------------
__global__ void scan4_kernel() {
    const int* cnt; int* off; int* cur; int n;
    switch (blockIdx.x) {
        case 0:  cnt = g_c_u2u;   off = g_off_u2u; cur = g_cur_u2u; n = NUc; break;
        case 1:  cnt = g_c_t2t;   off = g_off_t2t; cur = g_cur_t2t; n = NTc; break;
        case 2:  cnt = g_c_u2t_d; off = g_off_u2t; cur = g_cur_u2t; n = NTc; break;
        default: cnt = g_c_t2u_d; off = g_off_t2u; cur = g_cur_t2u; n = NUc; break;
    }
    __shared__ int sh[1024];
    int tid = threadIdx.x;
    int chunk = (n + 1023) >> 10;
    int start = tid * chunk;
    int end = min(start + chunk, n);
    int s = 0;
    for (int i = start; i < end; i++) s += cnt[i];
    sh[tid] = s;
    __syncthreads();
    for (int d = 1; d < 1024; d <<= 1) {
        int v = (tid >= d) ? sh[tid - d] : 0;
        __syncthreads();
        sh[tid] += v;
        __syncthreads();
    }
    int run = sh[tid] - s;   // exclusive prefix of this chunk
    for (int i = start; i < end; i++) { off[i] = run; cur[i] = run; run += cnt[i]; }
    if (start < n && end == n) off[n] = run;
}

// ---------------- setup: CSR fill ----------------
__global__ void fill_kernel(const int* __restrict__ eu2u, const int* __restrict__ et2t,
                            const int* __restrict__ eu2t, const int* __restrict__ et2u) {
    int e = blockIdx.x * blockDim.x + threadIdx.x;
    if (e >= Ec) return;
    int p;
    p = atomicAdd(&g_cur_u2u[eu2u[Ec + e]], 1); g_csr_u2u[p] = eu2u[e];
    p = atomicAdd(&g_cur_t2t[et2t[Ec + e]], 1); g_csr_t2t[p] = et2t[e];
    p = atomicAdd(&g_cur_u2t[eu2t[Ec + e]], 1); g_csr_u2t[p] = eu2t[e];
    p = atomicAdd(&g_cur_t2u[et2u[Ec + e]], 1); g_csr_t2u[p] = et2u[e];
}

__global__ void dinv_kernel() {
    int i = blockIdx.x * blockDim.x + threadIdx.x;
    if (i < NUc) {
        g_d_u2u[i] = rsqrtf((float)g_c_u2u[i] + 1.f);
        int cs = g_c_u2t_s[i]; g_ds_u2t[i] = (cs > 0) ? rsqrtf((float)cs) : 0.f;
        int cd = g_c_t2u_d[i]; g_dd_t2u[i] = (cd > 0) ? rsqrtf((float)cd) : 0.f;
    }
    if (i < NTc) {
        g_d_t2t[i] = rsqrtf((float)g_c_t2t[i] + 1.f);
        int cd = g_c_u2t_d[i]; g_dd_u2t[i] = (cd > 0) ? rsqrtf((float)cd) : 0.f;
        int cs = g_c_t2u_s[i]; g_ds_t2u[i] = (cs > 0) ? rsqrtf((float)cs) : 0.f;
    }
}

// ---------------- tf32 tensor-core GEMM core: 128-row tile, K=64, N=64 ----------------
template<bool DUAL>
__device__ __forceinline__ void mma_gemm64(const float* __restrict__ A,
                                           const float* __restrict__ W0,
                                           const float* __restrict__ W1,
                                           const float* __restrict__ sc0,
                                           const float* __restrict__ sc1,
                                           const float* __restrict__ bias,
                                           u32* __restrict__ O0h,
                                           u32* __restrict__ O1h,
                                           float* __restrict__ O0f,
                                           int N, int tile) {
    extern __shared__ float sm[];
    float* Wf0 = sm;
    float* Wf1 = DUAL ? (sm + 4096) : sm;
    float* As  = sm + (DUAL ? 8192 : 4096);   // 128*72 floats; reused as staging
    int t = threadIdx.x;
    int lane = t & 31, wid = t >> 5;
    int row0 = tile * 128;

    // pack weight fragments
    for (int i = t; i < 2048; i += 256) {
        int kk = i >> 8, rem = i & 255;
        int nt = rem >> 5, ln = rem & 31;
        int k0 = ln & 3, n = ln >> 2;
        int col = nt * 8 + n, k = kk * 8 + k0;
        float2 v;
        v.x = __uint_as_float(f2tf(W0[k * 64 + col]));
        v.y = __uint_as_float(f2tf(W0[(k + 4) * 64 + col]));
        *(float2*)&Wf0[(size_t)i * 2] = v;
        if (DUAL) {
            v.x = __uint_as_float(f2tf(W1[k * 64 + col]));
            v.y = __uint_as_float(f2tf(W1[(k + 4) * 64 + col]));
            *(float2*)&Wf1[(size_t)i * 2] = v;
        }
    }
    // load + convert A tile
    for (int i = t; i < 128 * 64; i += 256) {
        int r = i >> 6, c = i & 63;
        int gr = row0 + r;
        float v = (gr < N) ? A[((size_t)gr << 6) + c] : 0.f;
        As[r * 72 + c] = __uint_as_float(f2tf(v));
    }
    __syncthreads();

    const u32* Asu = (const u32*)As;
    int rbase = wid * 16;
    int fr = lane >> 2, fc = lane & 3;

    float acc0[8][4];
    float acc1[DUAL ? 8 : 1][4];
#pragma unroll
    for (int nt = 0; nt < 8; nt++)
#pragma unroll
        for (int j = 0; j < 4; j++) { acc0[nt][j] = 0.f; if (DUAL) acc1[nt][j] = 0.f; }

#pragma unroll
    for (int kk = 0; kk < 8; kk++) {
        int base = (rbase + fr) * 72 + kk * 8 + fc;
        u32 a0 = Asu[base];
        u32 a1 = Asu[base + 8 * 72];
        u32 a2 = Asu[base + 4];
        u32 a3 = Asu[base + 8 * 72 + 4];
#pragma unroll
        for (int nt = 0; nt < 8; nt++) {
            float2 b = *(const float2*)&Wf0[(size_t)(((kk << 3) + nt) << 5 | lane) * 2];
            mma_tf32(acc0[nt], a0, a1, a2, a3, __float_as_uint(b.x), __float_as_uint(b.y));
            if (DUAL) {
                float2 c = *(const float2*)&Wf1[(size_t)(((kk << 3) + nt) << 5 | lane) * 2];
                mma_tf32(acc1[nt], a0, a1, a2, a3, __float_as_uint(c.x), __float_as_uint(c.y));
            }
        }
    }

    // ---- epilogue: stage D through smem, coalesced stores ----
    float* st = As;
    __syncthreads();
#pragma unroll
    for (int nt = 0; nt < 8; nt++) {
        int cbase = nt * 8 + fc * 2;
        *(float2*)&st[(rbase + fr) * 72 + cbase]     = make_float2(acc0[nt][0], acc0[nt][1]);
        *(float2*)&st[(rbase + fr + 8) * 72 + cbase] = make_float2(acc0[nt][2], acc0[nt][3]);
    }
    __syncthreads();
    for (int i = t; i < 128 * 16; i += 256) {
        int r = i >> 4, c4 = (i & 15) << 2;
        int gr = row0 + r;
        if (gr < N) {
            float4 v = *(float4*)&st[r * 72 + c4];
            if (!DUAL) {
                float4 bv = *(const float4*)(bias + c4);
                v.x += bv.x; v.y += bv.y; v.z += bv.z; v.w += bv.w;
                *(float4*)&O0f[((size_t)gr << 6) + c4] = v;
            } else {
                float s = sc0[gr];
                __half2 h0 = __floats2half2_rn(v.x * s, v.y * s);
                __half2 h1 = __floats2half2_rn(v.z * s, v.w * s);
                uint2 pk;
                pk.x = *(u32*)&h0; pk.y = *(u32*)&h1;
                *(uint2*)&O0h[((size_t)gr << 5) + (c4 >> 1)] = pk;
            }
        }
    }
    if (DUAL) {
        __syncthreads();
#pragma unroll
        for (int nt = 0; nt < 8; nt++) {
            int cbase = nt * 8 + fc * 2;
            *(float2*)&st[(rbase + fr) * 72 + cbase]     = make_float2(acc1[nt][0], acc1[nt][1]);
            *(float2*)&st[(rbase + fr + 8) * 72 + cbase] = make_float2(acc1[nt][2], acc1[nt][3]);
        }
        __syncthreads();
        for (int i = t; i < 128 * 16; i += 256) {
            int r = i >> 4, c4 = (i & 15) << 2;
            int gr = row0 + r;
            if (gr < N) {
                float4 v = *(float4*)&st[r * 72 + c4];
                float s = sc1[gr];
                __half2 h0 = __floats2half2_rn(v.x * s, v.y * s);
                __half2 h1 = __floats2half2_rn(v.z * s, v.w * s);
                uint2 pk;
                pk.x = *(u32*)&h0; pk.y = *(u32*)&h1;
                *(uint2*)&O1h[((size_t)gr << 5) + (c4 >> 1)] = pk;
            }
        }
    }
}

#define GU_T ((NUc + 127) / 128)
#define GT_T ((NTc + 127) / 128)

// merged transforms for one layer: u tiles then t tiles
__global__ void __launch_bounds__(256) transform_kernel(const float* __restrict__ W) {
    int b = blockIdx.x;
    if (b < GU_T) {
        mma_gemm64<true>(g_hu, W + 0 * 4096, W + 2 * 4096, g_d_u2u, g_ds_u2t, nullptr,
                         g_mu0h, g_mu1h, nullptr, NUc, b);
    } else {
        mma_gemm64<true>(g_ht, W + 1 * 4096, W + 3 * 4096, g_d_t2t, g_ds_t2u, nullptr,
                         g_mt0h, g_mt1h, nullptr, NTc, b - GU_T);
    }
}

__global__ void __launch_bounds__(256) embed_txn_kernel(const float* __restrict__ x,
                                                        const float* __restrict__ W,
                                                        const float* __restrict__ b) {
    mma_gemm64<false>(x, W, nullptr, nullptr, nullptr, b, nullptr, nullptr, g_ht,
                      NTc, blockIdx.x);
}

// ---------------- fp32 embed for K=32 (small, one-time) ----------------
__global__ void __launch_bounds__(256) embed_user_kernel(const float* __restrict__ A,
                                                         const float* __restrict__ W,
                                                         const float* __restrict__ b) {
    const int K = 32;
    __shared__ float Ws[K * 64];
    __shared__ float As[32 * (K + 1)];
    int t = threadIdx.x;
    for (int i = t; i < K * 64; i += 256) Ws[i] = W[i];
    int row0 = blockIdx.x * 32;
    for (int i = t; i < 32 * K; i += 256) {
        int r = i / K, c = i - r * K; int gr = row0 + r;
        As[r * (K + 1) + c] = (gr < NUc) ? A[(size_t)gr * K + c] : 0.f;
    }
    __syncthreads();
    int r = t >> 3, cseg = (t & 7) << 3;
    float acc[8];
#pragma unroll
    for (int i = 0; i < 8; i++) acc[i] = b[cseg + i];
#pragma unroll
    for (int k = 0; k < K; k++) {
        float a = As[r * (K + 1) + k];
#pragma unroll
        for (int i = 0; i < 8; i++) acc[i] += a * Ws[(k << 6) + cseg + i];
    }
    int gr = row0 + r;
    if (gr < NUc) {
        float4* p = (float4*)(g_hu + ((size_t)gr << 6) + cseg);
        p[0] = make_float4(acc[0], acc[1], acc[2], acc[3]);
        p[1] = make_float4(acc[4], acc[5], acc[6], acc[7]);
    }
}

// ---------------- fused gather-aggregate + bias + relu (fp16 messages) ----------------
// 8 threads/node, one uint4 (8 halves) each.
// 4-edge batches summed as fp16 pairwise trees (depth 2), then folded into fp32.
__device__ __forceinline__ void gather_loop(float* acc, const u32* __restrict__ m,
                                            const int* __restrict__ csr,
                                            int e, int end, int woff) {
    for (; e + 4 <= end; e += 4) {
        int s0 = __ldg(csr + e), s1 = __ldg(csr + e + 1);
        int s2 = __ldg(csr + e + 2), s3 = __ldg(csr + e + 3);
        uint4 x0 = __ldg((const uint4*)(m + ((size_t)s0 << 5) + woff));
        uint4 x1 = __ldg((const uint4*)(m + ((size_t)s1 << 5) + woff));
        uint4 x2 = __ldg((const uint4*)(m + ((size_t)s2 << 5) + woff));
        uint4 x3 = __ldg((const uint4*)(m + ((size_t)s3 << 5) + woff));
        uint4 t = h2add4(h2add4(x0, x1), h2add4(x2, x3));
        acc_h8(acc, t);
    }
    for (; e < end; e++) {
        int s = __ldg(csr + e);
        acc_h8(acc, __ldg((const uint4*)(m + ((size_t)s << 5) + woff)));
    }
}

__device__ __forceinline__ void agg_body(int idx,
                                         const u32* __restrict__ mA,
                                         const int* __restrict__ offA,
                                         const int* __restrict__ csrA,
                                         const float* __restrict__ dA,
                                         const u32* __restrict__ mB,
                                         const int* __restrict__ offB,
                                         const int* __restrict__ csrB,
                                         const float* __restrict__ dB,
                                         const float* __restrict__ bA,
                                         const float* __restrict__ bB,
                                         float* __restrict__ Out, int N) {
    int g = idx >> 3;
    if (g >= N) return;
    int q = idx & 7;              // 8 columns per thread: one uint4 = 8 halves
    int woff = q << 2;            // u32 offset within row (row = 32 u32)
    float a[8], b[8];
    // self term (relation A includes self loop)
    {
        uint4 v = __ldg((const uint4*)(mA + ((size_t)g << 5) + woff));
        float2 f;
        f = __half22float2(*(__half2*)&v.x); a[0] = f.x; a[1] = f.y;
        f = __half22float2(*(__half2*)&v.y); a[2] = f.x; a[3] = f.y;
        f = __half22float2(*(__half2*)&v.z); a[4] = f.x; a[5] = f.y;
        f = __half22float2(*(__half2*)&v.w); a[6] = f.x; a[7] = f.y;
    }
#pragma unroll
    for (int i = 0; i < 8; i++) b[i] = 0.f;
    gather_loop(a, mA, csrA, offA[g], offA[g + 1], woff);
    gather_loop(b, mB, csrB, offB[g], offB[g + 1], woff);
    float da = dA[g], db = dB[g];
    int c0 = q << 3;
    float4 bAv0 = __ldg((const float4*)(bA + c0)), bAv1 = __ldg((const float4*)(bA + c0 + 4));
    float4 bBv0 = __ldg((const float4*)(bB + c0)), bBv1 = __ldg((const float4*)(bB + c0 + 4));
    float4 o0, o1;
    o0.x = fmaxf(0.5f * (da * a[0] + db * b[0] + bAv0.x + bBv0.x), 0.f);
    o0.y = fmaxf(0.5f * (da * a[1] + db * b[1] + bAv0.y + bBv0.y), 0.f);
    o0.z = fmaxf(0.5f * (da * a[2] + db * b[2] + bAv0.z + bBv0.z), 0.f);
    o0.w = fmaxf(0.5f * (da * a[3] + db * b[3] + bAv0.w + bBv0.w), 0.f);
    o1.x = fmaxf(0.5f * (da * a[4] + db * b[4] + bAv1.x + bBv1.x), 0.f);
    o1.y = fmaxf(0.5f * (da * a[5] + db * b[5] + bAv1.y + bBv1.y), 0.f);
    o1.z = fmaxf(0.5f * (da * a[6] + db * b[6] + bAv1.z + bBv1.z), 0.f);
    o1.w = fmaxf(0.5f * (da * a[7] + db * b[7] + bAv1.w + bBv1.w), 0.f);
    float4* op = (float4*)(Out + ((size_t)g << 6) + c0);
    op[0] = o0; op[1] = o1;
}

#define AU_B ((NUc * 8 + 255) / 256)
#define AT_B ((NTc * 8 + 255) / 256)

__global__ void __launch_bounds__(256) agg_kernel(const float* __restrict__ B) {
    int b = blockIdx.x;
    if (b < AU_B) {
        agg_body(b * 256 + threadIdx.x,
                 g_mu0h, g_off_u2u, g_csr_u2u, g_d_u2u,
                 g_mt1h, g_off_t2u, g_csr_t2u, g_dd_t2u,
                 B + 0 * 64, B + 3 * 64, g_hu, NUc);
    } else {
        agg_body((b - AU_B) * 256 + threadIdx.x,
                 g_mt0h, g_off_t2t, g_csr_t2t, g_d_t2t,
                 g_mu1h, g_off_u2t, g_csr_u2t, g_dd_u2t,
                 B + 1 * 64, B + 2 * 64, g_ht, NTc);
    }
}

// ---------------- readout ----------------
#define CS_BLOCKS 296
__global__ void colsum_kernel() {
    int b = blockIdx.x;
    if (b < CS_BLOCKS) {
        int t = b * blockDim.x + threadIdx.x;
        float s = 0.f;
        const int n = NUc * 64;
        for (int i = t; i < n; i += CS_BLOCKS * 256) s += g_hu[i];
        atomicAdd(&g_colsum[t & 63], s);
    } else {
        int t = (b - CS_BLOCKS) * blockDim.x + threadIdx.x;
        float s = 0.f;
        const int n = NTc * 64;
        for (int i = t; i < n; i += CS_BLOCKS * 256) s += g_ht[i];
        atomicAdd(&g_colsum[64 + (t & 63)], s);
    }
}

__global__ void mlp_kernel(const float* __restrict__ W1, const float* __restrict__ b1,
                           const float* __restrict__ W2, const float* __restrict__ b2,
                           float* __restrict__ out) {
    __shared__ float x[64];
    __shared__ float y[64];
    int t = threadIdx.x;
    x[t] = 0.5f * (g_colsum[t] * (1.f / NUc) + g_colsum[64 + t] * (1.f / NTc));
    __syncthreads();
    float s = b1[t];
    for (int k = 0; k < 64; k++) s += x[k] * W1[k * 64 + t];
    y[t] = fmaxf(s, 0.f) * W2[t];
    __syncthreads();
    if (t == 0) {
        float o = b2[0];
        for (int j = 0; j < 64; j++) o += y[j];
        out[0] = 1.f / (1.f + expf(-o));
    }
}

// ---------------- launch ----------------
extern "C" void kernel_launch(void* const* d_in, const int* in_sizes, int n_in,
                              void* d_out, int out_size) {
    const float* x_user     = (const float*)d_in[0];
    const float* x_txn      = (const float*)d_in[1];
    const int*   ei_u2u     = (const int*)d_in[2];
    const int*   ei_t2t     = (const int*)d_in[3];
    const int*   ei_u2t     = (const int*)d_in[4];
    const int*   ei_t2u     = (const int*)d_in[5];
    const float* W_emb_user = (const float*)d_in[6];
    const float* b_emb_user = (const float*)d_in[7];
    const float* W_emb_txn  = (const float*)d_in[8];
    const float* b_emb_txn  = (const float*)d_in[9];
    const float* conv_W     = (const float*)d_in[10];
    const float* conv_b     = (const float*)d_in[11];
    const float* W1         = (const float*)d_in[12];
    const float* b1         = (const float*)d_in[13];
    const float* W2         = (const float*)d_in[14];
    const float* b2         = (const float*)d_in[15];
    float* out = (float*)d_out;

    const int SMEM_DUAL = (2 * 4096 + 128 * 72) * 4;   // 69632
    const int SMEM_SNGL = (4096 + 128 * 72) * 4;       // 53248
    cudaFuncSetAttribute(transform_kernel, cudaFuncAttributeMaxDynamicSharedMemorySize, SMEM_DUAL);
    cudaFuncSetAttribute(embed_txn_kernel, cudaFuncAttributeMaxDynamicSharedMemorySize, SMEM_SNGL);

    // ---- CSR + norms (edge structure is layer-invariant) ----
    zero_cnt_kernel<<<(NTc + 255) / 256, 256>>>();
    count_kernel<<<(Ec + 255) / 256, 256>>>(ei_u2u, ei_t2t, ei_u2t, ei_t2u);
    scan4_kernel<<<4, 1024>>>();
    fill_kernel<<<(Ec + 255) / 256, 256>>>(ei_u2u, ei_t2t, ei_u2t, ei_t2u);
    dinv_kernel<<<(NTc + 255) / 256, 256>>>();

    // ---- embeddings ----
    embed_user_kernel<<<(NUc + 31) / 32, 256>>>(x_user, W_emb_user, b_emb_user);
    embed_txn_kernel<<<GT_T, 256, SMEM_SNGL>>>(x_txn, W_emb_txn, b_emb_txn);

    // ---- layers ----
    for (int l = 0; l < 3; l++) {
        const float* W = conv_W + (size_t)l * 4 * 64 * 64;
        const float* B = conv_b + (size_t)l * 4 * 64;
        transform_kernel<<<GU_T + GT_T, 256, SMEM_DUAL>>>(W);
        agg_kernel<<<AU_B + AT_B, 256>>>(B);
    }

    // ---- readout ----
    colsum_kernel<<<2 * CS_BLOCKS, 256>>>();
    mlp_kernel<<<1, 64>>>(W1, b1, W2, b2, out);
}